// round 4
// baseline (speedup 1.0000x reference)
#include <cuda_runtime.h>

#define Nn 100000
#define Ee 1600000
#define ENt 1700000
#define C 128
#define NEG 0.2f
#define BN_EPS 1e-5
#define NB1 98            // ceil(Nn/1024)

// ---------------- scratch (device globals; no allocation allowed) ----------------
__device__ int      g_is64;
__device__ int      g_src[ENt];
__device__ int      g_dst[ENt];
__device__ int      g_deg[Nn];
__device__ int      g_rowstart[Nn + 1];
__device__ int      g_cursor[Nn];
__device__ int      g_csrc[ENt];
__device__ int      g_bsum[NB1];
__device__ int      g_boff[128];
__device__ __align__(16) float g_h[(size_t)Nn * C];
__device__ __align__(16) float g_agg[(size_t)Nn * C];
__device__ float    g_ssrc[Nn];
__device__ float    g_sdst[Nn];
__device__ double   g_sum[C];
__device__ double   g_sumsq[C];
__device__ float    g_a[C];
__device__ float    g_b[C];

// ---------------- one-time CSR build ----------------

// Detect whether edge_index is int64 or int32: for int64 nonneg values < 2^31,
// every odd int32 word (hi word, little-endian) is 0. For int32 data those words
// are random node ids.
__global__ void k_detect(const int* __restrict__ ei32) {
    __shared__ int nz;
    if (threadIdx.x == 0) nz = 0;
    __syncthreads();
    if (ei32[2 * threadIdx.x + 1] != 0) atomicAdd(&nz, 1);
    __syncthreads();
    if (threadIdx.x == 0) g_is64 = (nz == 0) ? 1 : 0;
}

__global__ void k_zerodeg() {
    int i = blockIdx.x * blockDim.x + threadIdx.x;
    if (i < Nn) g_deg[i] = 0;
}

// Decode edges (either dtype), append self loops, histogram degrees by dst.
__global__ void k_convert(const void* __restrict__ eiv) {
    int i = blockIdx.x * blockDim.x + threadIdx.x;
    if (i >= ENt) return;
    int s, d;
    if (i < Ee) {
        if (g_is64) {
            const long long* e = (const long long*)eiv;
            s = (int)e[i];
            d = (int)e[Ee + i];
        } else {
            const int* e = (const int*)eiv;
            s = e[i];
            d = e[Ee + i];
        }
        s = min(max(s, 0), Nn - 1);
        d = min(max(d, 0), Nn - 1);
    } else {
        s = i - Ee;
        d = i - Ee;
    }
    g_src[i] = s;
    g_dst[i] = d;
    atomicAdd(&g_deg[d], 1);
}

// Per-block inclusive scan of degrees (1024/block).
__global__ void k_scan1() {
    __shared__ int sh[1024];
    int t = threadIdx.x;
    int i = blockIdx.x * 1024 + t;
    int v = (i < Nn) ? g_deg[i] : 0;
    sh[t] = v;
    __syncthreads();
    for (int o = 1; o < 1024; o <<= 1) {
        int tv = (t >= o) ? sh[t - o] : 0;
        __syncthreads();
        if (t >= o) sh[t] += tv;
        __syncthreads();
    }
    if (i < Nn) g_rowstart[i + 1] = sh[t];
    if (t == 1023) g_bsum[blockIdx.x] = sh[1023];
}

// Scan of block sums (single block of 128 threads).
__global__ void k_scan2() {
    __shared__ int sh[128];
    int t = threadIdx.x;
    int v = (t < NB1) ? g_bsum[t] : 0;
    sh[t] = v;
    __syncthreads();
    for (int o = 1; o < 128; o <<= 1) {
        int tv = (t >= o) ? sh[t - o] : 0;
        __syncthreads();
        if (t >= o) sh[t] += tv;
        __syncthreads();
    }
    g_boff[t] = sh[t] - v;   // exclusive
}

// Add block offsets; produce rowstart + cursor.
__global__ void k_scan3() {
    int i = blockIdx.x * blockDim.x + threadIdx.x;
    if (i >= Nn) return;
    int v = g_rowstart[i + 1] + g_boff[i >> 10];
    g_rowstart[i + 1] = v;
    if (i + 1 < Nn) g_cursor[i + 1] = v;
    if (i == 0) { g_rowstart[0] = 0; g_cursor[0] = 0; }
}

__global__ void k_scatter() {
    int e = blockIdx.x * blockDim.x + threadIdx.x;
    if (e >= ENt) return;
    int d = g_dst[e];
    int slot = atomicAdd(&g_cursor[d], 1);
    g_csrc[slot] = g_src[e];
}

// ---------------- per-layer kernels ----------------

__global__ void k_zstats() {
    int c = threadIdx.x;
    g_sum[c] = 0.0;
    g_sumsq[c] = 0.0;
}

// h = x @ W, fused attention logits s_src = h.a_src, s_dst = h.a_dst.
__global__ void k_gemm(const float* __restrict__ x, int ldx, const float* __restrict__ W,
                       const float* __restrict__ asrc, const float* __restrict__ adst) {
    extern __shared__ float sm[];
    float* Wsh = sm;               // 128*128
    float* Xsh = sm + 128 * 128;   // 64*128
    int t = threadIdx.x;           // 256 threads
    int row0 = blockIdx.x * 64;

    const float4* W4 = (const float4*)W;
    float4* Ws4 = (float4*)Wsh;
    #pragma unroll 4
    for (int i = t; i < 4096; i += 256) Ws4[i] = W4[i];

    float4* Xs4 = (float4*)Xsh;
    #pragma unroll 2
    for (int i = t; i < 2048; i += 256) {
        int r = i >> 5, c4 = i & 31;
        int gr = row0 + r;
        float4 v = make_float4(0.f, 0.f, 0.f, 0.f);
        if (gr < Nn) v = *(const float4*)(x + (size_t)gr * ldx + c4 * 4);
        Xs4[i] = v;
    }
    __syncthreads();

    int tx = t & 31, ty = t >> 5;          // warp ty handles rows ty*8..ty*8+7
    float acc[8][4];
    #pragma unroll
    for (int i = 0; i < 8; i++)
        acc[i][0] = acc[i][1] = acc[i][2] = acc[i][3] = 0.f;

    const float* xrow = Xsh + (ty * 8) * 128;
    #pragma unroll 4
    for (int k = 0; k < 128; k++) {
        float4 b = *(const float4*)(Wsh + k * 128 + tx * 4);
        #pragma unroll
        for (int i = 0; i < 8; i++) {
            float a = xrow[i * 128 + k];
            acc[i][0] += a * b.x;
            acc[i][1] += a * b.y;
            acc[i][2] += a * b.z;
            acc[i][3] += a * b.w;
        }
    }

    float4 va = ((const float4*)asrc)[tx];
    float4 vb = ((const float4*)adst)[tx];
    #pragma unroll
    for (int i = 0; i < 8; i++) {
        int gr = row0 + ty * 8 + i;
        if (gr < Nn)
            *(float4*)(g_h + (size_t)gr * 128 + tx * 4) =
                make_float4(acc[i][0], acc[i][1], acc[i][2], acc[i][3]);
        float s1 = acc[i][0] * va.x + acc[i][1] * va.y + acc[i][2] * va.z + acc[i][3] * va.w;
        float s2 = acc[i][0] * vb.x + acc[i][1] * vb.y + acc[i][2] * vb.z + acc[i][3] * vb.w;
        #pragma unroll
        for (int o = 16; o; o >>= 1) {
            s1 += __shfl_down_sync(0xffffffffu, s1, o);
            s2 += __shfl_down_sync(0xffffffffu, s2, o);
        }
        if (tx == 0 && gr < Nn) { g_ssrc[gr] = s1; g_sdst[gr] = s2; }
    }
}

// Fused softmax + aggregation: one warp per destination node. No atomics.
__global__ void k_agg(const float* __restrict__ bias) {
    int gt = blockIdx.x * blockDim.x + threadIdx.x;
    int w = gt >> 5, lane = gt & 31;
    if (w >= Nn) return;
    int j0 = g_rowstart[w], j1 = g_rowstart[w + 1];
    float sd = g_sdst[w];

    // pass 1: segment max
    float m = -1e30f;
    for (int j = j0 + lane; j < j1; j += 32) {
        float v = g_ssrc[g_csrc[j]] + sd;
        v = v > 0.f ? v : NEG * v;
        m = fmaxf(m, v);
    }
    #pragma unroll
    for (int o = 16; o; o >>= 1) m = fmaxf(m, __shfl_xor_sync(0xffffffffu, m, o));

    // pass 2: segment sum of exp
    float sum = 0.f;
    for (int j = j0 + lane; j < j1; j += 32) {
        float v = g_ssrc[g_csrc[j]] + sd;
        v = v > 0.f ? v : NEG * v;
        sum += __expf(v - m);
    }
    #pragma unroll
    for (int o = 16; o; o >>= 1) sum += __shfl_xor_sync(0xffffffffu, sum, o);
    float inv = __fdividef(1.f, sum);

    // pass 3: gather alpha * h[src]; each lane owns 4 contiguous channels
    float4 acc = make_float4(0.f, 0.f, 0.f, 0.f);
    for (int j = j0; j < j1; j++) {
        int s = g_csrc[j];
        float v = g_ssrc[s] + sd;
        v = v > 0.f ? v : NEG * v;
        float a = __expf(v - m) * inv;
        float4 hv = ((const float4*)(g_h + (size_t)s * 128))[lane];
        acc.x += a * hv.x;
        acc.y += a * hv.y;
        acc.z += a * hv.z;
        acc.w += a * hv.w;
    }
    float4 bi = ((const float4*)bias)[lane];
    float4 o;
    o.x = fmaxf(acc.x + bi.x, 0.f);
    o.y = fmaxf(acc.y + bi.y, 0.f);
    o.z = fmaxf(acc.z + bi.z, 0.f);
    o.w = fmaxf(acc.w + bi.w, 0.f);
    ((float4*)(g_agg + (size_t)w * 128))[lane] = o;
}

// BN stats over post-relu values in g_agg.
__global__ void k_stats() {
    int c = threadIdx.x;               // 128 threads = channels
    int r0 = blockIdx.x * 128;
    int r1 = min(r0 + 128, Nn);
    float s = 0.f, s2 = 0.f;
    for (int r = r0; r < r1; r++) {
        float v = g_agg[(size_t)r * 128 + c];
        s += v; s2 += v * v;
    }
    atomicAdd(&g_sum[c], (double)s);
    atomicAdd(&g_sumsq[c], (double)s2);
}

__global__ void k_finalize(const float* __restrict__ gamma, const float* __restrict__ beta) {
    int c = threadIdx.x;
    double mu  = g_sum[c] / (double)Nn;
    double var = g_sumsq[c] / (double)Nn - mu * mu;
    float rs = (float)(1.0 / sqrt(var + BN_EPS));
    float a = gamma[c] * rs;
    g_a[c] = a;
    g_b[c] = beta[c] - a * (float)mu;
}

// Apply BN, write into strided d_out slice.
__global__ void k_norm(float* __restrict__ out, int l) {
    int i = blockIdx.x * blockDim.x + threadIdx.x;
    if (i >= Nn * 32) return;
    int r = i >> 5, c4 = i & 31;
    float4 v = ((const float4*)g_agg)[i];
    int c = c4 * 4;
    float4 o;
    o.x = v.x * g_a[c + 0] + g_b[c + 0];
    o.y = v.y * g_a[c + 1] + g_b[c + 1];
    o.z = v.z * g_a[c + 2] + g_b[c + 2];
    o.w = v.w * g_a[c + 3] + g_b[c + 3];
    *(float4*)(out + (size_t)r * 384 + l * 128 + c) = o;
}

// ---------------- launch ----------------
extern "C" void kernel_launch(void* const* d_in, const int* in_sizes, int n_in,
                              void* d_out, int out_size) {
    const float* x     = (const float*)d_in[0];
    const void*  ei    = d_in[1];
    const float* Ws    = (const float*)d_in[2];
    const float* asrc  = (const float*)d_in[3];
    const float* adst  = (const float*)d_in[4];
    const float* bias  = (const float*)d_in[5];
    const float* gamma = (const float*)d_in[6];
    const float* beta  = (const float*)d_in[7];
    float* out = (float*)d_out;

    cudaFuncSetAttribute(k_gemm, cudaFuncAttributeMaxDynamicSharedMemorySize, 96 * 1024);

    // one-time CSR build
    k_detect<<<1, 256>>>((const int*)ei);
    k_zerodeg<<<(Nn + 255) / 256, 256>>>();
    k_convert<<<(ENt + 255) / 256, 256>>>(ei);
    k_scan1<<<NB1, 1024>>>();
    k_scan2<<<1, 128>>>();
    k_scan3<<<(Nn + 255) / 256, 256>>>();
    k_scatter<<<(ENt + 255) / 256, 256>>>();

    for (int l = 0; l < 3; l++) {
        const float* xin = (l == 0) ? x : (out + (size_t)(l - 1) * 128);
        int ldx = (l == 0) ? 128 : 384;

        k_zstats<<<1, 128>>>();
        k_gemm<<<(Nn + 63) / 64, 256, 96 * 1024>>>(xin, ldx, Ws + (size_t)l * C * C,
                                                   asrc + l * C, adst + l * C);
        k_agg<<<(Nn * 32 + 255) / 256, 256>>>(bias + l * C);
        k_stats<<<(Nn + 127) / 128, 128>>>();
        k_finalize<<<1, 128>>>(gamma + l * C, beta + l * C);
        k_norm<<<(Nn * 32 + 255) / 256, 256>>>(out, l);
    }
}